// round 15
// baseline (speedup 1.0000x reference)
#include <cuda_runtime.h>
#include <cuda_bf16.h>
#include <cstdint>

// ---------------------------------------------------------------------------
// NeuralODE persistent kernel, round 15:
//  512 threads / 16 warps = 2 m-tiles x 8 n-groups; each warp owns ONE m-tile
//  (halves A-fragment smem traffic again). G2/G3 in fp8 e4m3 QMMA (validated
//  numerics: x16 scale, 1/256 fold), G1 bf16 HMMA with W1-B from smem planes.
//  W2/W3 fp8 fragments register-resident (64+16 u32); biases in smem; 128-reg
//  cap at 512 threads, 4 warps/SMSP for real latency hiding.
// ---------------------------------------------------------------------------

namespace {

constexpr int B_    = 4096;
constexpr int S_    = 64;
constexpr int H_    = 256;
constexpr int MROWS = 32;              // rows per CTA
constexpr int CTAS  = B_ / MROWS;      // 128
constexpr int NTH   = 512;             // 16 warps

constexpr int XSTR  = 36;              // x tile u32 stride (stride%8==4)
constexpr int HS    = 272;             // h tile BYTE stride (272%128==16)

// smem layout (bytes)
constexpr int SM_X    = 0;                     // 32*36*4 = 4608
constexpr int SM_H1   = 4608;                  // 32*272  = 8704
constexpr int SM_H2   = 13312;                 // 8704
constexpr int SM_W1P0 = 22016;                 // 16384
constexpr int SM_W1P1 = 38400;                 // 16384
constexpr int SM_B1   = 54784;                 // 1024
constexpr int SM_B2   = 55808;                 // 1024
constexpr int SMEM_BYTES = 56832 + 256;

__device__ __forceinline__ uint32_t pack_bf16(float lo, float hi) {
    __nv_bfloat162 v = __floats2bfloat162_rn(lo, hi);
    return *reinterpret_cast<uint32_t*>(&v);
}

// f32 pair -> f16x2 -> tanh -> *16 -> e4m3x2 (u16: low byte = lo, high = hi)
__device__ __forceinline__ uint16_t tanh16_e4m3(float hi, float lo) {
    uint32_t ph, th, ts;
    uint16_t e;
    asm("cvt.rn.f16x2.f32 %0, %1, %2;" : "=r"(ph) : "f"(hi), "f"(lo));
    asm("tanh.approx.f16x2 %0, %1;" : "=r"(th) : "r"(ph));
    asm("mul.rn.f16x2 %0, %1, %2;" : "=r"(ts) : "r"(th), "r"(0x4C004C00u)); // *16
    asm("cvt.rn.satfinite.e4m3x2.f16x2 %0, %1;" : "=h"(e) : "r"(ts));
    return e;
}

// pack 4 f32 (already scaled) into 4 e4m3 bytes, k-ascending byte order
__device__ __forceinline__ uint32_t pk_e4m3x4(float f0, float f1, float f2, float f3) {
    uint16_t lo, hi;
    uint32_t d;
    asm("cvt.rn.satfinite.e4m3x2.f32 %0, %1, %2;" : "=h"(lo) : "f"(f1), "f"(f0));
    asm("cvt.rn.satfinite.e4m3x2.f32 %0, %1, %2;" : "=h"(hi) : "f"(f3), "f"(f2));
    asm("mov.b32 %0, {%1, %2};" : "=r"(d) : "h"(lo), "h"(hi));
    return d;
}

__device__ __forceinline__ void ldsm_x4(uint32_t& r0, uint32_t& r1,
                                        uint32_t& r2, uint32_t& r3,
                                        uint32_t addr) {
    asm volatile("ldmatrix.sync.aligned.m8n8.x4.shared.b16 {%0,%1,%2,%3}, [%4];"
                 : "=r"(r0), "=r"(r1), "=r"(r2), "=r"(r3) : "r"(addr));
}

__device__ __forceinline__ void mma16816(float* d,
                                         uint32_t a0, uint32_t a1, uint32_t a2, uint32_t a3,
                                         uint32_t b0, uint32_t b1) {
    asm volatile(
        "mma.sync.aligned.m16n8k16.row.col.f32.bf16.bf16.f32 "
        "{%0,%1,%2,%3},{%4,%5,%6,%7},{%8,%9},{%0,%1,%2,%3};\n"
        : "+f"(d[0]), "+f"(d[1]), "+f"(d[2]), "+f"(d[3])
        : "r"(a0), "r"(a1), "r"(a2), "r"(a3), "r"(b0), "r"(b1));
}

__device__ __forceinline__ void qmma(float* d,
                                     uint32_t a0, uint32_t a1, uint32_t a2, uint32_t a3,
                                     uint32_t b0, uint32_t b1) {
    asm volatile(
        "mma.sync.aligned.m16n8k32.row.col.f32.e4m3.e4m3.f32 "
        "{%0,%1,%2,%3},{%4,%5,%6,%7},{%8,%9},{%0,%1,%2,%3};\n"
        : "+f"(d[0]), "+f"(d[1]), "+f"(d[2]), "+f"(d[3])
        : "r"(a0), "r"(a1), "r"(a2), "r"(a3), "r"(b0), "r"(b1));
}

// Shuffle fp32 W[K][N] (row-major) into one bf16x2 B-fragment plane.
//   idx = ((nt*NKB + kb)*4 + t)*8 + g ; n = nt*8+g ; k0 = kb*16 + t*2 + koff
template <int NKB, int LOG2NKB>
__device__ void fill_plane(uint32_t* plane, const float* __restrict__ W,
                           int N, int koff, int tid) {
    const int total = N * NKB * 4;
    for (int e = tid; e < total; e += NTH) {
        int gg   = e & 7;
        int tt   = (e >> 3) & 3;
        int kbnt = e >> 5;
        int kb   = kbnt & (NKB - 1);
        int nt   = kbnt >> LOG2NKB;
        int n    = nt * 8 + gg;
        int k0   = kb * 16 + tt * 2 + koff;
        plane[e] = pack_bf16(W[k0 * N + n], W[(k0 + 1) * N + n]);
    }
}

} // namespace

extern "C" __global__ void __launch_bounds__(NTH, 1)
neuralode_persistent_kernel(const float* __restrict__ x0,
                            const float* __restrict__ W1, const float* __restrict__ b1,
                            const float* __restrict__ W2, const float* __restrict__ b2,
                            const float* __restrict__ W3, const float* __restrict__ b3,
                            const float* __restrict__ dt_scale,
                            const int*   __restrict__ num_steps,
                            float* __restrict__ out)
{
    extern __shared__ unsigned char smem_raw[];
    uint32_t* xb   = reinterpret_cast<uint32_t*>(smem_raw + SM_X);
    uint32_t* w1p0 = reinterpret_cast<uint32_t*>(smem_raw + SM_W1P0);
    uint32_t* w1p1 = reinterpret_cast<uint32_t*>(smem_raw + SM_W1P1);
    float*    sb1  = reinterpret_cast<float*>(smem_raw + SM_B1);
    float*    sb2  = reinterpret_cast<float*>(smem_raw + SM_B2);

    const int tid  = threadIdx.x;
    const int lane = tid & 31;
    const int g = lane >> 2, t = lane & 3;
    const int wid = tid >> 5;              // 0..15
    const int mt  = wid & 1;               // m-tile (16 rows)
    const int ng  = wid >> 1;              // n-group 0..7
    const int tg  = t * 8 + g;

    const int   nsteps  = num_steps[0];
    const float dts     = dt_scale[0] * 0.01f;
    const float dts256  = dts * (1.0f / 256.0f);
    const float inv256  = 1.0f / 256.0f;
    const int   row0    = blockIdx.x * MROWS;
    const long  ostride = (long)(nsteps + 1) * S_;

    // ---- t=0: trajectory[., 0, .] = x0 ----
    for (int i = tid; i < MROWS * S_; i += NTH) {
        int r = i >> 6, c = i & 63;
        out[(long)(row0 + r) * ostride + c] = x0[(row0 + r) * S_ + c];
    }

    // ---- one-time W1 plane shuffle + biases into smem ----
    fill_plane<4, 2>(w1p0, W1, H_, 0, tid);
    fill_plane<4, 2>(w1p1, W1, H_, 8, tid);
    if (tid < H_) { sb1[tid] = b1[tid]; sb2[tid] = b2[tid]; }

    // ---- register-resident fp8 weight fragments ----
    // W2 (e4m3, x16): 4 n-tiles x 8 kb x 2 halves = 64 u32
    uint32_t wb2a[4][8], wb2b[4][8];
#pragma unroll
    for (int j = 0; j < 4; ++j) {
        int n = ng * 32 + j * 8 + g;
#pragma unroll
        for (int kb = 0; kb < 8; ++kb) {
            int k0 = kb * 32 + 4 * t;
            wb2a[j][kb] = pk_e4m3x4(16.f * W2[k0 * H_ + n],      16.f * W2[(k0+1) * H_ + n],
                                    16.f * W2[(k0+2) * H_ + n],  16.f * W2[(k0+3) * H_ + n]);
            wb2b[j][kb] = pk_e4m3x4(16.f * W2[(k0+16) * H_ + n], 16.f * W2[(k0+17) * H_ + n],
                                    16.f * W2[(k0+18) * H_ + n], 16.f * W2[(k0+19) * H_ + n]);
        }
    }
    // W3 (e4m3, x16): 1 n-tile = 16 u32
    uint32_t wb3a[8], wb3b[8];
    {
        int n = ng * 8 + g;
#pragma unroll
        for (int kb = 0; kb < 8; ++kb) {
            int k0 = kb * 32 + 4 * t;
            wb3a[kb] = pk_e4m3x4(16.f * W3[k0 * S_ + n],      16.f * W3[(k0+1) * S_ + n],
                                 16.f * W3[(k0+2) * S_ + n],  16.f * W3[(k0+3) * S_ + n]);
            wb3b[kb] = pk_e4m3x4(16.f * W3[(k0+16) * S_ + n], 16.f * W3[(k0+17) * S_ + n],
                                 16.f * W3[(k0+18) * S_ + n], 16.f * W3[(k0+19) * S_ + n]);
        }
    }

    // b3*dts (2 regs)
    float pb3d[2];
    {
        int c = ng * 8 + t * 2;
        pb3d[0] = b3[c] * dts;  pb3d[1] = b3[c + 1] * dts;
    }

    // ---- ldmatrix addresses (own m-tile only) ----
    const int q     = lane >> 3;
    const int rrow  = (lane & 7) | ((q & 1) << 3);   // 0..15
    const uint32_t sbase = (uint32_t)__cvta_generic_to_shared(smem_raw);
    const uint32_t xba = sbase + SM_X  + ((mt * 16 + rrow) * XSTR + ((q >> 1) << 2)) * 4;
    const uint32_t h1a = sbase + SM_H1 + (mt * 16 + rrow) * HS + (q >> 1) * 16;
    const uint32_t h2a = sbase + SM_H2 + (mt * 16 + rrow) * HS + (q >> 1) * 16;

    // ---- x state registers (own m-tile, own 8 cols) + x tile (bf16) ----
    float xr[4];
    {
        int r = mt * 16 + g;
        int colb = ng * 8 + t * 2;
        const float* p = x0 + (long)(row0 + r) * S_ + colb;
        xr[0] = p[0];
        xr[1] = p[1];
        xr[2] = p[8 * S_];
        xr[3] = p[8 * S_ + 1];
        int pidx = ng * 4 + t;
        xb[r * XSTR + pidx]       = pack_bf16(xr[0], xr[1]);
        xb[(r + 8) * XSTR + pidx] = pack_bf16(xr[2], xr[3]);
    }
    __syncthreads();

    // ======================= main time-step loop ==========================
    for (int step = 0; step < nsteps; ++step) {
        float acc[4][4];

        // ---- GEMM1 (bf16): [16,64] @ W1[64,256], B from smem planes ----
#pragma unroll
        for (int j = 0; j < 4; ++j)
#pragma unroll
            for (int u = 0; u < 4; ++u) acc[j][u] = 0.f;

#pragma unroll
        for (int kb = 0; kb < 4; ++kb) {
            uint32_t a0, a1v, a2, a3;
            ldsm_x4(a0, a1v, a2, a3, xba + kb * 32);
#pragma unroll
            for (int j = 0; j < 4; ++j) {
                int idx = ((ng * 4 + j) * 4 + kb) * 32 + tg;
                mma16816(acc[j], a0, a1v, a2, a3, w1p0[idx], w1p1[idx]);
            }
        }
        // E1: h1 = e4m3(16 * tanh(acc + b1))
#pragma unroll
        for (int j = 0; j < 4; ++j) {
            int col = ng * 32 + j * 8 + 2 * t;
            float bb0 = sb1[col], bb1 = sb1[col + 1];
            int r = mt * 16 + g;
            *reinterpret_cast<uint16_t*>(smem_raw + SM_H1 + r * HS + col) =
                tanh16_e4m3(acc[j][1] + bb1, acc[j][0] + bb0);
            *reinterpret_cast<uint16_t*>(smem_raw + SM_H1 + (r + 8) * HS + col) =
                tanh16_e4m3(acc[j][3] + bb1, acc[j][2] + bb0);
        }
        __syncthreads();   // bar A: h1 ready

        // ---- GEMM2 (e4m3): [16,256] @ W2[256,256], acc = 256*true ----
#pragma unroll
        for (int j = 0; j < 4; ++j)
#pragma unroll
            for (int u = 0; u < 4; ++u) acc[j][u] = 0.f;

#pragma unroll
        for (int kb = 0; kb < 8; ++kb) {
            uint32_t a0, a1v, a2, a3;
            ldsm_x4(a0, a1v, a2, a3, h1a + kb * 32);
#pragma unroll
            for (int j = 0; j < 4; ++j)
                qmma(acc[j], a0, a1v, a2, a3, wb2a[j][kb], wb2b[j][kb]);
        }

        // E2: h2 = e4m3(16 * tanh(acc/256 + b2))  (distinct buffer)
#pragma unroll
        for (int j = 0; j < 4; ++j) {
            int col = ng * 32 + j * 8 + 2 * t;
            float bb0 = sb2[col], bb1 = sb2[col + 1];
            float a0 = fmaf(acc[j][0], inv256, bb0);
            float a1 = fmaf(acc[j][1], inv256, bb1);
            float a2 = fmaf(acc[j][2], inv256, bb0);
            float a3 = fmaf(acc[j][3], inv256, bb1);
            int r = mt * 16 + g;
            *reinterpret_cast<uint16_t*>(smem_raw + SM_H2 + r * HS + col) =
                tanh16_e4m3(a1, a0);
            *reinterpret_cast<uint16_t*>(smem_raw + SM_H2 + (r + 8) * HS + col) =
                tanh16_e4m3(a3, a2);
        }
        __syncthreads();   // bar B: h2 ready

        // ---- GEMM3 (e4m3): [16,256] @ W3[256,64], acc3 = 256*(dx - b3) ----
        float acc3[4];
#pragma unroll
        for (int u = 0; u < 4; ++u) acc3[u] = 0.f;

#pragma unroll
        for (int kb = 0; kb < 8; ++kb) {
            uint32_t a0, a1v, a2, a3;
            ldsm_x4(a0, a1v, a2, a3, h2a + kb * 32);
            qmma(acc3, a0, a1v, a2, a3, wb3a[kb], wb3b[kb]);
        }

        // E3: x += acc3*dts/256 + b3*dts ; store trajectory + refresh xb
        {
            int r = mt * 16 + g;
            int colb = ng * 8 + t * 2;
            xr[0] += fmaf(acc3[0], dts256, pb3d[0]);
            xr[1] += fmaf(acc3[1], dts256, pb3d[1]);
            xr[2] += fmaf(acc3[2], dts256, pb3d[0]);
            xr[3] += fmaf(acc3[3], dts256, pb3d[1]);
            float* orow = out + (long)(row0 + r) * ostride
                        + (long)(step + 1) * S_ + colb;
            __stcs(reinterpret_cast<float2*>(orow),
                   make_float2(xr[0], xr[1]));
            __stcs(reinterpret_cast<float2*>(orow + 8 * ostride),
                   make_float2(xr[2], xr[3]));
            int pidx = ng * 4 + t;
            xb[r * XSTR + pidx]       = pack_bf16(xr[0], xr[1]);
            xb[(r + 8) * XSTR + pidx] = pack_bf16(xr[2], xr[3]);
        }
        __syncthreads();   // bar C: xb ready for next step
    }
}

extern "C" void kernel_launch(void* const* d_in, const int* in_sizes, int n_in,
                              void* d_out, int out_size)
{
    (void)in_sizes; (void)n_in; (void)out_size;
    const float* x0       = (const float*)d_in[0];
    const float* W1       = (const float*)d_in[1];
    const float* b1       = (const float*)d_in[2];
    const float* W2       = (const float*)d_in[3];
    const float* b2       = (const float*)d_in[4];
    const float* W3       = (const float*)d_in[5];
    const float* b3       = (const float*)d_in[6];
    const float* dt_scale = (const float*)d_in[7];
    const int*   nsteps   = (const int*)d_in[8];
    float*       out      = (float*)d_out;

    cudaFuncSetAttribute(neuralode_persistent_kernel,
                         cudaFuncAttributeMaxDynamicSharedMemorySize, SMEM_BYTES);
    neuralode_persistent_kernel<<<CTAS, NTH, SMEM_BYTES>>>(
        x0, W1, b1, W2, b2, W3, b3, dt_scale, nsteps, out);
}

// round 16
// speedup vs baseline: 1.7509x; 1.7509x over previous
#include <cuda_runtime.h>
#include <cuda_bf16.h>
#include <cstdint>

// ---------------------------------------------------------------------------
// NeuralODE persistent kernel, round 16:
//  R5 (best: 565us) + channel-permuted h tiles.
//  The h1/h2 channel order is permuted (within each 16-pair block, stored
//  pair p' = t*4 + j instead of j*4 + t) so each thread's 4 epilogue outputs
//  per row are CONTIGUOUS -> one STS.128 per row (4 per epilogue vs 16
//  STS.32). A 16B-chunk XOR swizzle (chunk ^ (row&7)) keeps ldmatrix reads
//  bank-conflict-free. W2/W3 register fragments are built from gmem with the
//  matching inverse k-permutation, so all dot products are unchanged.
// ---------------------------------------------------------------------------

namespace {

constexpr int B_    = 4096;
constexpr int S_    = 64;
constexpr int H_    = 256;
constexpr int MROWS = 32;              // rows per CTA
constexpr int CTAS  = B_ / MROWS;      // 128
constexpr int NTH   = 256;             // 8 warps

constexpr int XSTR  = 36;              // x tile u32 stride (stride%8==4)
constexpr int HROW  = 512;             // h tile row stride in BYTES (32 chunks)

// smem layout (bytes, 128-aligned)
constexpr int SM_X    = 0;                     // 32*36*4 = 4608
constexpr int SM_H1   = 4608;                  // 32*512  = 16384
constexpr int SM_H2   = 20992;                 // 16384
constexpr int SM_W1P0 = 37376;                 // 16384
constexpr int SM_W1P1 = 53760;                 // 16384
constexpr int SMEM_BYTES = 70144 + 256;

__device__ __forceinline__ uint32_t pack_bf16(float lo, float hi) {
    __nv_bfloat162 v = __floats2bfloat162_rn(lo, hi);
    return *reinterpret_cast<uint32_t*>(&v);
}

__device__ __forceinline__ uint32_t tanh_bf16x2(uint32_t v) {
    uint32_t r;
    asm("tanh.approx.bf16x2 %0, %1;" : "=r"(r) : "r"(v));
    return r;
}

__device__ __forceinline__ void ldsm_x4(uint32_t& r0, uint32_t& r1,
                                        uint32_t& r2, uint32_t& r3,
                                        uint32_t addr) {
    asm volatile("ldmatrix.sync.aligned.m8n8.x4.shared.b16 {%0,%1,%2,%3}, [%4];"
                 : "=r"(r0), "=r"(r1), "=r"(r2), "=r"(r3) : "r"(addr));
}

__device__ __forceinline__ void mma16816(float* d,
                                         uint32_t a0, uint32_t a1, uint32_t a2, uint32_t a3,
                                         uint32_t b0, uint32_t b1) {
    asm volatile(
        "mma.sync.aligned.m16n8k16.row.col.f32.bf16.bf16.f32 "
        "{%0,%1,%2,%3},{%4,%5,%6,%7},{%8,%9},{%0,%1,%2,%3};\n"
        : "+f"(d[0]), "+f"(d[1]), "+f"(d[2]), "+f"(d[3])
        : "r"(a0), "r"(a1), "r"(a2), "r"(a3), "r"(b0), "r"(b1));
}

// Shuffle fp32 W[K][N] (row-major) into one bf16x2 B-fragment plane (W1 only).
template <int NKB, int LOG2NKB>
__device__ void fill_plane(uint32_t* plane, const float* __restrict__ W,
                           int N, int koff, int tid) {
    const int total = N * NKB * 4;
    for (int e = tid; e < total; e += NTH) {
        int gg   = e & 7;
        int tt   = (e >> 3) & 3;
        int kbnt = e >> 5;
        int kb   = kbnt & (NKB - 1);
        int nt   = kbnt >> LOG2NKB;
        int n    = nt * 8 + gg;
        int k0   = kb * 16 + tt * 2 + koff;
        plane[e] = pack_bf16(W[k0 * N + n], W[(k0 + 1) * N + n]);
    }
}

} // namespace

extern "C" __global__ void __launch_bounds__(NTH, 1)
neuralode_persistent_kernel(const float* __restrict__ x0,
                            const float* __restrict__ W1, const float* __restrict__ b1,
                            const float* __restrict__ W2, const float* __restrict__ b2,
                            const float* __restrict__ W3, const float* __restrict__ b3,
                            const float* __restrict__ dt_scale,
                            const int*   __restrict__ num_steps,
                            float* __restrict__ out)
{
    extern __shared__ unsigned char smem_raw[];
    uint32_t* xb   = reinterpret_cast<uint32_t*>(smem_raw + SM_X);
    uint32_t* w1p0 = reinterpret_cast<uint32_t*>(smem_raw + SM_W1P0);
    uint32_t* w1p1 = reinterpret_cast<uint32_t*>(smem_raw + SM_W1P1);

    const int tid  = threadIdx.x;
    const int lane = tid & 31;
    const int g = lane >> 2, t = lane & 3;
    const int ng = tid >> 5;               // warp = n-column group 0..7
    const int tg = t * 8 + g;

    const int   nsteps  = num_steps[0];
    const float dts     = dt_scale[0] * 0.01f;
    const int   row0    = blockIdx.x * MROWS;
    const long  ostride = (long)(nsteps + 1) * S_;

    // ---- one-time W1 plane shuffle ----
    fill_plane<4, 2>(w1p0, W1, H_, 0, tid);
    fill_plane<4, 2>(w1p1, W1, H_, 8, tid);

    // ---- t=0: trajectory[., 0, .] = x0 ----
    for (int i = tid; i < MROWS * S_; i += NTH) {
        int r = i >> 6, c = i & 63;
        out[(long)(row0 + r) * ostride + c] = x0[(row0 + r) * S_ + c];
    }

    // ---- register-resident W2/W3 fragments, built with the PERMUTED k ----
    // Stored pair p' = blk*16 + t_w*4 + j_w holds channel pair blk*16 + j_w*4 + t_w.
    // For MMA block kb, thread t: first pair p'=kb*8+t -> channel k0a,
    // second pair p'=kb*8+t+4 -> channel k0a+2, with
    //   k0a = (kb>>1)*32 + t*8 + 4*(kb&1).
    uint32_t wb2a[4][16], wb2b[4][16];
#pragma unroll
    for (int j = 0; j < 4; ++j) {
        int n = (ng * 4 + j) * 8 + g;
#pragma unroll
        for (int kb = 0; kb < 16; ++kb) {
            int k0a = (kb >> 1) * 32 + t * 8 + 4 * (kb & 1);
            wb2a[j][kb] = pack_bf16(W2[k0a * H_ + n],       W2[(k0a + 1) * H_ + n]);
            wb2b[j][kb] = pack_bf16(W2[(k0a + 2) * H_ + n], W2[(k0a + 3) * H_ + n]);
        }
    }
    uint32_t wb3a[16], wb3b[16];
    {
        int n = ng * 8 + g;
#pragma unroll
        for (int kb = 0; kb < 16; ++kb) {
            int k0a = (kb >> 1) * 32 + t * 8 + 4 * (kb & 1);
            wb3a[kb] = pack_bf16(W3[k0a * S_ + n],       W3[(k0a + 1) * S_ + n]);
            wb3b[kb] = pack_bf16(W3[(k0a + 2) * S_ + n], W3[(k0a + 3) * S_ + n]);
        }
    }

    // ---- register-resident biases ----
    float pb1[4][2], pb2[4][2], pb3[2];
#pragma unroll
    for (int j = 0; j < 4; ++j) {
        int c = (ng * 4 + j) * 8 + t * 2;
        pb1[j][0] = b1[c];  pb1[j][1] = b1[c + 1];
        pb2[j][0] = b2[c];  pb2[j][1] = b2[c + 1];
    }
    {
        int c = ng * 8 + t * 2;
        pb3[0] = b3[c];  pb3[1] = b3[c + 1];
    }

    // ---- ldmatrix addresses ----
    const int q     = lane >> 3;
    const int rrow  = (lane & 7) | ((q & 1) << 3);   // 0..15
    const int qh    = q >> 1;                        // k-half chunk select
    const uint32_t sbase = (uint32_t)__cvta_generic_to_shared(smem_raw);
    uint32_t xba[2], h1b[2], h2b[2];
    int rx[2];
#pragma unroll
    for (int mt = 0; mt < 2; ++mt) {
        int rr = mt * 16 + rrow;
        xba[mt] = sbase + SM_X + (rr * XSTR + (qh << 2)) * 4;
        h1b[mt] = sbase + SM_H1 + rr * HROW;
        h2b[mt] = sbase + SM_H2 + rr * HROW;
        rx[mt]  = rr & 7;
    }

    // ---- x state registers + x tile (bf16, un-permuted) ----
    float xr[2][4];
#pragma unroll
    for (int mt = 0; mt < 2; ++mt) {
        int r = mt * 16 + g;
        int colb = ng * 8 + t * 2;
        const float* p = x0 + (long)(row0 + r) * S_ + colb;
        xr[mt][0] = p[0];
        xr[mt][1] = p[1];
        xr[mt][2] = p[8 * S_];
        xr[mt][3] = p[8 * S_ + 1];
        int pidx = ng * 4 + t;
        xb[r * XSTR + pidx]       = pack_bf16(xr[mt][0], xr[mt][1]);
        xb[(r + 8) * XSTR + pidx] = pack_bf16(xr[mt][2], xr[mt][3]);
    }
    __syncthreads();   // W1 planes + x tile ready

    // epilogue store chunk index: thread's 4 outputs (j=0..3) are contiguous
    // at stored chunk (ng*4 + t), XOR-swizzled by row&7 (= g for both rows).
    const int echunk = ((ng * 4 + t) ^ g) * 16;

    // ======================= main time-step loop ==========================
    for (int step = 0; step < nsteps; ++step) {
        float acc[2][4][4];

        // ---- GEMM1 (bf16): [32,64] @ W1[64,256], B from smem planes ----
#pragma unroll
        for (int mt = 0; mt < 2; ++mt)
#pragma unroll
            for (int j = 0; j < 4; ++j)
#pragma unroll
                for (int u = 0; u < 4; ++u) acc[mt][j][u] = 0.f;

#pragma unroll
        for (int kb = 0; kb < 4; ++kb) {
            uint32_t a[2][4];
#pragma unroll
            for (int mt = 0; mt < 2; ++mt)
                ldsm_x4(a[mt][0], a[mt][1], a[mt][2], a[mt][3], xba[mt] + kb * 32);
#pragma unroll
            for (int j = 0; j < 4; ++j) {
                int idx = ((ng * 4 + j) * 4 + kb) * 32 + tg;
                uint32_t b0 = w1p0[idx], b1f = w1p1[idx];
#pragma unroll
                for (int mt = 0; mt < 2; ++mt)
                    mma16816(acc[mt][j], a[mt][0], a[mt][1], a[mt][2], a[mt][3],
                             b0, b1f);
            }
        }
        // E1: h1 = tanh(acc + b1), permuted layout, one STS.128 per row
#pragma unroll
        for (int mt = 0; mt < 2; ++mt) {
            int r = mt * 16 + g;
            uint4 v0, v1;
            v0.x = tanh_bf16x2(pack_bf16(acc[mt][0][0] + pb1[0][0], acc[mt][0][1] + pb1[0][1]));
            v0.y = tanh_bf16x2(pack_bf16(acc[mt][1][0] + pb1[1][0], acc[mt][1][1] + pb1[1][1]));
            v0.z = tanh_bf16x2(pack_bf16(acc[mt][2][0] + pb1[2][0], acc[mt][2][1] + pb1[2][1]));
            v0.w = tanh_bf16x2(pack_bf16(acc[mt][3][0] + pb1[3][0], acc[mt][3][1] + pb1[3][1]));
            v1.x = tanh_bf16x2(pack_bf16(acc[mt][0][2] + pb1[0][0], acc[mt][0][3] + pb1[0][1]));
            v1.y = tanh_bf16x2(pack_bf16(acc[mt][1][2] + pb1[1][0], acc[mt][1][3] + pb1[1][1]));
            v1.z = tanh_bf16x2(pack_bf16(acc[mt][2][2] + pb1[2][0], acc[mt][2][3] + pb1[2][1]));
            v1.w = tanh_bf16x2(pack_bf16(acc[mt][3][2] + pb1[3][0], acc[mt][3][3] + pb1[3][1]));
            *reinterpret_cast<uint4*>(smem_raw + SM_H1 + r * HROW + echunk) = v0;
            *reinterpret_cast<uint4*>(smem_raw + SM_H1 + (r + 8) * HROW + echunk) = v1;
        }
        __syncthreads();   // bar A: h1 ready

        // ---- GEMM2 (bf16): [32,256] @ W2[256,256], permuted A + B frags ----
#pragma unroll
        for (int mt = 0; mt < 2; ++mt)
#pragma unroll
            for (int j = 0; j < 4; ++j)
#pragma unroll
                for (int u = 0; u < 4; ++u) acc[mt][j][u] = 0.f;

#pragma unroll
        for (int kb = 0; kb < 16; ++kb) {
            uint32_t a[2][4];
#pragma unroll
            for (int mt = 0; mt < 2; ++mt) {
                int ch = ((2 * kb + qh) ^ rx[mt]) << 4;
                ldsm_x4(a[mt][0], a[mt][1], a[mt][2], a[mt][3], h1b[mt] + ch);
            }
#pragma unroll
            for (int j = 0; j < 4; ++j)
#pragma unroll
                for (int mt = 0; mt < 2; ++mt)
                    mma16816(acc[mt][j], a[mt][0], a[mt][1], a[mt][2], a[mt][3],
                             wb2a[j][kb], wb2b[j][kb]);
        }

        // E2: h2 = tanh(acc + b2), same permuted layout (distinct buffer)
#pragma unroll
        for (int mt = 0; mt < 2; ++mt) {
            int r = mt * 16 + g;
            uint4 v0, v1;
            v0.x = tanh_bf16x2(pack_bf16(acc[mt][0][0] + pb2[0][0], acc[mt][0][1] + pb2[0][1]));
            v0.y = tanh_bf16x2(pack_bf16(acc[mt][1][0] + pb2[1][0], acc[mt][1][1] + pb2[1][1]));
            v0.z = tanh_bf16x2(pack_bf16(acc[mt][2][0] + pb2[2][0], acc[mt][2][1] + pb2[2][1]));
            v0.w = tanh_bf16x2(pack_bf16(acc[mt][3][0] + pb2[3][0], acc[mt][3][1] + pb2[3][1]));
            v1.x = tanh_bf16x2(pack_bf16(acc[mt][0][2] + pb2[0][0], acc[mt][0][3] + pb2[0][1]));
            v1.y = tanh_bf16x2(pack_bf16(acc[mt][1][2] + pb2[1][0], acc[mt][1][3] + pb2[1][1]));
            v1.z = tanh_bf16x2(pack_bf16(acc[mt][2][2] + pb2[2][0], acc[mt][2][3] + pb2[2][1]));
            v1.w = tanh_bf16x2(pack_bf16(acc[mt][3][2] + pb2[3][0], acc[mt][3][3] + pb2[3][1]));
            *reinterpret_cast<uint4*>(smem_raw + SM_H2 + r * HROW + echunk) = v0;
            *reinterpret_cast<uint4*>(smem_raw + SM_H2 + (r + 8) * HROW + echunk) = v1;
        }
        __syncthreads();   // bar B: h2 ready

        // ---- GEMM3 (bf16): [32,256] @ W3[256,64] ----
        float acc3[2][4];
#pragma unroll
        for (int mt = 0; mt < 2; ++mt)
#pragma unroll
            for (int u = 0; u < 4; ++u) acc3[mt][u] = 0.f;

#pragma unroll
        for (int kb = 0; kb < 16; ++kb) {
#pragma unroll
            for (int mt = 0; mt < 2; ++mt) {
                int ch = ((2 * kb + qh) ^ rx[mt]) << 4;
                uint32_t a0, a1v, a2, a3;
                ldsm_x4(a0, a1v, a2, a3, h2b[mt] + ch);
                mma16816(acc3[mt], a0, a1v, a2, a3, wb3a[kb], wb3b[kb]);
            }
        }

        // E3: x += (acc3 + b3) * dts ; trajectory store + xb refresh
#pragma unroll
        for (int mt = 0; mt < 2; ++mt) {
            int r = mt * 16 + g;
            int colb = ng * 8 + t * 2;
            xr[mt][0] += (acc3[mt][0] + pb3[0]) * dts;
            xr[mt][1] += (acc3[mt][1] + pb3[1]) * dts;
            xr[mt][2] += (acc3[mt][2] + pb3[0]) * dts;
            xr[mt][3] += (acc3[mt][3] + pb3[1]) * dts;
            float* orow = out + (long)(row0 + r) * ostride
                        + (long)(step + 1) * S_ + colb;
            __stcs(reinterpret_cast<float2*>(orow),
                   make_float2(xr[mt][0], xr[mt][1]));
            __stcs(reinterpret_cast<float2*>(orow + 8 * ostride),
                   make_float2(xr[mt][2], xr[mt][3]));
            int pidx = ng * 4 + t;
            xb[r * XSTR + pidx]       = pack_bf16(xr[mt][0], xr[mt][1]);
            xb[(r + 8) * XSTR + pidx] = pack_bf16(xr[mt][2], xr[mt][3]);
        }
        __syncthreads();   // bar C: xb ready for next step
    }
}

extern "C" void kernel_launch(void* const* d_in, const int* in_sizes, int n_in,
                              void* d_out, int out_size)
{
    (void)in_sizes; (void)n_in; (void)out_size;
    const float* x0       = (const float*)d_in[0];
    const float* W1       = (const float*)d_in[1];
    const float* b1       = (const float*)d_in[2];
    const float* W2       = (const float*)d_in[3];
    const float* b2       = (const float*)d_in[4];
    const float* W3       = (const float*)d_in[5];
    const float* b3       = (const float*)d_in[6];
    const float* dt_scale = (const float*)d_in[7];
    const int*   nsteps   = (const int*)d_in[8];
    float*       out      = (float*)d_out;

    cudaFuncSetAttribute(neuralode_persistent_kernel,
                         cudaFuncAttributeMaxDynamicSharedMemorySize, SMEM_BYTES);
    neuralode_persistent_kernel<<<CTAS, NTH, SMEM_BYTES>>>(
        x0, W1, b1, W2, b2, W3, b3, dt_scale, nsteps, out);
}

// round 17
// speedup vs baseline: 1.8038x; 1.0302x over previous
#include <cuda_runtime.h>
#include <cuda_bf16.h>
#include <cstdint>

// ---------------------------------------------------------------------------
// NeuralODE persistent kernel, round 17:
//  R5 (best: 565us) + register relief + explicit LDSM/MMA software pipelining.
//   - W3 B-fragments moved back to smem planes (-32 regs, ~1KB/step traffic)
//   - b1/b2 biases in smem (-16 regs)
//   - W2 register fragments loaded directly from gmem (no staging planes)
//   - all GEMM k-loops double-buffer A-fragments: ldsm(kb+1) issued before
//     the kb MMA burst, so crossbar latency hides under tensor work.
// ---------------------------------------------------------------------------

namespace {

constexpr int B_    = 4096;
constexpr int S_    = 64;
constexpr int H_    = 256;
constexpr int MROWS = 32;              // rows per CTA
constexpr int CTAS  = B_ / MROWS;      // 128
constexpr int NTH   = 256;             // 8 warps

constexpr int XSTR  = 36;              // x tile u32 stride (stride%8==4)
constexpr int HSTR  = 132;             // h tile u32 stride (stride%8==4)

// smem layout (bytes)
constexpr int SM_W1P0 = 0;                       // 16384
constexpr int SM_W1P1 = 16384;                   // 16384
constexpr int SM_W3P0 = 32768;                   // 16384
constexpr int SM_W3P1 = 49152;                   // 16384
constexpr int SM_H1   = 65536;                   // 32*132*4 = 16896
constexpr int SM_H2   = 82432;                   // 16896
constexpr int SM_XB   = 99328;                   // 32*36*4 = 4608
constexpr int SM_B1   = 103936;                  // 1024
constexpr int SM_B2   = 104960;                  // 1024
constexpr int SMEM_BYTES = 105984 + 256;

__device__ __forceinline__ uint32_t pack_bf16(float lo, float hi) {
    __nv_bfloat162 v = __floats2bfloat162_rn(lo, hi);
    return *reinterpret_cast<uint32_t*>(&v);
}

__device__ __forceinline__ uint32_t tanh_bf16x2(uint32_t v) {
    uint32_t r;
    asm("tanh.approx.bf16x2 %0, %1;" : "=r"(r) : "r"(v));
    return r;
}

__device__ __forceinline__ void ldsm_x4(uint32_t& r0, uint32_t& r1,
                                        uint32_t& r2, uint32_t& r3,
                                        uint32_t addr) {
    asm volatile("ldmatrix.sync.aligned.m8n8.x4.shared.b16 {%0,%1,%2,%3}, [%4];"
                 : "=r"(r0), "=r"(r1), "=r"(r2), "=r"(r3) : "r"(addr));
}

__device__ __forceinline__ void mma16816(float* d,
                                         uint32_t a0, uint32_t a1, uint32_t a2, uint32_t a3,
                                         uint32_t b0, uint32_t b1) {
    asm volatile(
        "mma.sync.aligned.m16n8k16.row.col.f32.bf16.bf16.f32 "
        "{%0,%1,%2,%3},{%4,%5,%6,%7},{%8,%9},{%0,%1,%2,%3};\n"
        : "+f"(d[0]), "+f"(d[1]), "+f"(d[2]), "+f"(d[3])
        : "r"(a0), "r"(a1), "r"(a2), "r"(a3), "r"(b0), "r"(b1));
}

// Shuffle fp32 W[K][N] (row-major) into one bf16x2 B-fragment plane.
//   idx = ((nt*NKB + kb)*4 + t)*8 + g ; n = nt*8+g ; k0 = kb*16 + t*2 + koff
template <int NKB, int LOG2NKB>
__device__ void fill_plane(uint32_t* plane, const float* __restrict__ W,
                           int N, int koff, int tid) {
    const int total = N * NKB * 4;
    for (int e = tid; e < total; e += NTH) {
        int gg   = e & 7;
        int tt   = (e >> 3) & 3;
        int kbnt = e >> 5;
        int kb   = kbnt & (NKB - 1);
        int nt   = kbnt >> LOG2NKB;
        int n    = nt * 8 + gg;
        int k0   = kb * 16 + tt * 2 + koff;
        plane[e] = pack_bf16(W[k0 * N + n], W[(k0 + 1) * N + n]);
    }
}

} // namespace

extern "C" __global__ void __launch_bounds__(NTH, 1)
neuralode_persistent_kernel(const float* __restrict__ x0,
                            const float* __restrict__ W1, const float* __restrict__ b1,
                            const float* __restrict__ W2, const float* __restrict__ b2,
                            const float* __restrict__ W3, const float* __restrict__ b3,
                            const float* __restrict__ dt_scale,
                            const int*   __restrict__ num_steps,
                            float* __restrict__ out)
{
    extern __shared__ unsigned char smem_raw[];
    uint32_t* w1p0 = reinterpret_cast<uint32_t*>(smem_raw + SM_W1P0);
    uint32_t* w1p1 = reinterpret_cast<uint32_t*>(smem_raw + SM_W1P1);
    uint32_t* w3p0 = reinterpret_cast<uint32_t*>(smem_raw + SM_W3P0);
    uint32_t* w3p1 = reinterpret_cast<uint32_t*>(smem_raw + SM_W3P1);
    uint32_t* h1buf= reinterpret_cast<uint32_t*>(smem_raw + SM_H1);
    uint32_t* h2buf= reinterpret_cast<uint32_t*>(smem_raw + SM_H2);
    uint32_t* xb   = reinterpret_cast<uint32_t*>(smem_raw + SM_XB);
    float*    sb1  = reinterpret_cast<float*>(smem_raw + SM_B1);
    float*    sb2  = reinterpret_cast<float*>(smem_raw + SM_B2);

    const int tid  = threadIdx.x;
    const int lane = tid & 31;
    const int g = lane >> 2, t = lane & 3;
    const int ng = tid >> 5;               // warp = n-column group 0..7
    const int tg = t * 8 + g;

    const int   nsteps  = num_steps[0];
    const float dts     = dt_scale[0] * 0.01f;
    const int   row0    = blockIdx.x * MROWS;
    const long  ostride = (long)(nsteps + 1) * S_;

    // ---- one-time plane shuffles + biases ----
    fill_plane<4, 2>(w1p0, W1, H_, 0, tid);
    fill_plane<4, 2>(w1p1, W1, H_, 8, tid);
    fill_plane<16, 4>(w3p0, W3, S_, 0, tid);
    fill_plane<16, 4>(w3p1, W3, S_, 8, tid);
    if (tid < H_) { sb1[tid] = b1[tid]; sb2[tid] = b2[tid]; }

    // ---- t=0: trajectory[., 0, .] = x0 ----
    for (int i = tid; i < MROWS * S_; i += NTH) {
        int r = i >> 6, c = i & 63;
        out[(long)(row0 + r) * ostride + c] = x0[(row0 + r) * S_ + c];
    }

    // ---- W2 B-fragments straight from gmem (register-resident) ----
    uint32_t wb2a[4][16], wb2b[4][16];
#pragma unroll
    for (int j = 0; j < 4; ++j) {
        int n = (ng * 4 + j) * 8 + g;
#pragma unroll
        for (int kb = 0; kb < 16; ++kb) {
            int k0 = kb * 16 + 2 * t;
            wb2a[j][kb] = pack_bf16(W2[k0 * H_ + n],       W2[(k0 + 1) * H_ + n]);
            wb2b[j][kb] = pack_bf16(W2[(k0 + 8) * H_ + n], W2[(k0 + 9) * H_ + n]);
        }
    }

    // b3 only (2 regs)
    float pb3[2];
    {
        int c = ng * 8 + t * 2;
        pb3[0] = b3[c];  pb3[1] = b3[c + 1];
    }

    // ---- ldmatrix addresses ----
    const int q     = lane >> 3;
    const int rrow  = (lane & 7) | ((q & 1) << 3);   // 0..15
    const int koffu = (q >> 1) << 2;                 // 0 or 4 u32
    const uint32_t sbase = (uint32_t)__cvta_generic_to_shared(smem_raw);
    uint32_t xba[2], h1a[2], h2a[2];
#pragma unroll
    for (int mt = 0; mt < 2; ++mt) {
        xba[mt] = sbase + SM_XB + ((mt * 16 + rrow) * XSTR + koffu) * 4;
        h1a[mt] = sbase + SM_H1 + ((mt * 16 + rrow) * HSTR + koffu) * 4;
        h2a[mt] = sbase + SM_H2 + ((mt * 16 + rrow) * HSTR + koffu) * 4;
    }

    // ---- x state registers + x tile (bf16) ----
    float xr[2][4];
#pragma unroll
    for (int mt = 0; mt < 2; ++mt) {
        int r = mt * 16 + g;
        int colb = ng * 8 + t * 2;
        const float* p = x0 + (long)(row0 + r) * S_ + colb;
        xr[mt][0] = p[0];
        xr[mt][1] = p[1];
        xr[mt][2] = p[8 * S_];
        xr[mt][3] = p[8 * S_ + 1];
        int pidx = ng * 4 + t;
        xb[r * XSTR + pidx]       = pack_bf16(xr[mt][0], xr[mt][1]);
        xb[(r + 8) * XSTR + pidx] = pack_bf16(xr[mt][2], xr[mt][3]);
    }
    __syncthreads();   // planes + biases + x tile ready

    // ======================= main time-step loop ==========================
    for (int step = 0; step < nsteps; ++step) {
        float acc[2][4][4];
        uint32_t a[2][2][4];   // [buf][mt][frag] double-buffer

        // ---- GEMM1 (bf16): [32,64] @ W1[64,256], pipelined ----
#pragma unroll
        for (int mt = 0; mt < 2; ++mt)
#pragma unroll
            for (int j = 0; j < 4; ++j)
#pragma unroll
                for (int u = 0; u < 4; ++u) acc[mt][j][u] = 0.f;

#pragma unroll
        for (int mt = 0; mt < 2; ++mt)
            ldsm_x4(a[0][mt][0], a[0][mt][1], a[0][mt][2], a[0][mt][3], xba[mt]);
#pragma unroll
        for (int kb = 0; kb < 4; ++kb) {
            const int cur = kb & 1, nxt = cur ^ 1;
            if (kb < 3) {
#pragma unroll
                for (int mt = 0; mt < 2; ++mt)
                    ldsm_x4(a[nxt][mt][0], a[nxt][mt][1], a[nxt][mt][2], a[nxt][mt][3],
                            xba[mt] + (kb + 1) * 32);
            }
#pragma unroll
            for (int j = 0; j < 4; ++j) {
                int idx = ((ng * 4 + j) * 4 + kb) * 32 + tg;
                uint32_t b0 = w1p0[idx], b1f = w1p1[idx];
#pragma unroll
                for (int mt = 0; mt < 2; ++mt)
                    mma16816(acc[mt][j], a[cur][mt][0], a[cur][mt][1],
                             a[cur][mt][2], a[cur][mt][3], b0, b1f);
            }
        }
        // E1: h1 = tanh(acc + b1)   (biases from smem)
#pragma unroll
        for (int mt = 0; mt < 2; ++mt)
#pragma unroll
            for (int j = 0; j < 4; ++j) {
                int col = (ng * 4 + j) * 8 + t * 2;
                float bb0 = sb1[col], bb1 = sb1[col + 1];
                int pidx = (ng * 4 + j) * 4 + t;
                int r = mt * 16 + g;
                h1buf[r * HSTR + pidx] =
                    tanh_bf16x2(pack_bf16(acc[mt][j][0] + bb0, acc[mt][j][1] + bb1));
                h1buf[(r + 8) * HSTR + pidx] =
                    tanh_bf16x2(pack_bf16(acc[mt][j][2] + bb0, acc[mt][j][3] + bb1));
            }
        __syncthreads();   // bar A: h1 ready

        // ---- GEMM2 (bf16): [32,256] @ W2[256,256], pipelined ----
#pragma unroll
        for (int mt = 0; mt < 2; ++mt)
#pragma unroll
            for (int j = 0; j < 4; ++j)
#pragma unroll
                for (int u = 0; u < 4; ++u) acc[mt][j][u] = 0.f;

#pragma unroll
        for (int mt = 0; mt < 2; ++mt)
            ldsm_x4(a[0][mt][0], a[0][mt][1], a[0][mt][2], a[0][mt][3], h1a[mt]);
#pragma unroll
        for (int kb = 0; kb < 16; ++kb) {
            const int cur = kb & 1, nxt = cur ^ 1;
            if (kb < 15) {
#pragma unroll
                for (int mt = 0; mt < 2; ++mt)
                    ldsm_x4(a[nxt][mt][0], a[nxt][mt][1], a[nxt][mt][2], a[nxt][mt][3],
                            h1a[mt] + (kb + 1) * 32);
            }
#pragma unroll
            for (int j = 0; j < 4; ++j)
#pragma unroll
                for (int mt = 0; mt < 2; ++mt)
                    mma16816(acc[mt][j], a[cur][mt][0], a[cur][mt][1],
                             a[cur][mt][2], a[cur][mt][3], wb2a[j][kb], wb2b[j][kb]);
        }

        // E2: h2 = tanh(acc + b2)   (distinct buffer -> no barrier first)
#pragma unroll
        for (int mt = 0; mt < 2; ++mt)
#pragma unroll
            for (int j = 0; j < 4; ++j) {
                int col = (ng * 4 + j) * 8 + t * 2;
                float bb0 = sb2[col], bb1 = sb2[col + 1];
                int pidx = (ng * 4 + j) * 4 + t;
                int r = mt * 16 + g;
                h2buf[r * HSTR + pidx] =
                    tanh_bf16x2(pack_bf16(acc[mt][j][0] + bb0, acc[mt][j][1] + bb1));
                h2buf[(r + 8) * HSTR + pidx] =
                    tanh_bf16x2(pack_bf16(acc[mt][j][2] + bb0, acc[mt][j][3] + bb1));
            }
        __syncthreads();   // bar B: h2 ready

        // ---- GEMM3 (bf16): [32,256] @ W3[256,64], B from smem, pipelined ----
        float acc3[2][4];
#pragma unroll
        for (int mt = 0; mt < 2; ++mt)
#pragma unroll
            for (int u = 0; u < 4; ++u) acc3[mt][u] = 0.f;

#pragma unroll
        for (int mt = 0; mt < 2; ++mt)
            ldsm_x4(a[0][mt][0], a[0][mt][1], a[0][mt][2], a[0][mt][3], h2a[mt]);
#pragma unroll
        for (int kb = 0; kb < 16; ++kb) {
            const int cur = kb & 1, nxt = cur ^ 1;
            if (kb < 15) {
#pragma unroll
                for (int mt = 0; mt < 2; ++mt)
                    ldsm_x4(a[nxt][mt][0], a[nxt][mt][1], a[nxt][mt][2], a[nxt][mt][3],
                            h2a[mt] + (kb + 1) * 32);
            }
            int idx = (ng * 16 + kb) * 32 + tg;
            uint32_t b0 = w3p0[idx], b1f = w3p1[idx];
#pragma unroll
            for (int mt = 0; mt < 2; ++mt)
                mma16816(acc3[mt], a[cur][mt][0], a[cur][mt][1],
                         a[cur][mt][2], a[cur][mt][3], b0, b1f);
        }

        // E3: x += (acc3 + b3) * dts ; trajectory store + xb refresh
#pragma unroll
        for (int mt = 0; mt < 2; ++mt) {
            int r = mt * 16 + g;
            int colb = ng * 8 + t * 2;
            xr[mt][0] += (acc3[mt][0] + pb3[0]) * dts;
            xr[mt][1] += (acc3[mt][1] + pb3[1]) * dts;
            xr[mt][2] += (acc3[mt][2] + pb3[0]) * dts;
            xr[mt][3] += (acc3[mt][3] + pb3[1]) * dts;
            float* orow = out + (long)(row0 + r) * ostride
                        + (long)(step + 1) * S_ + colb;
            __stcs(reinterpret_cast<float2*>(orow),
                   make_float2(xr[mt][0], xr[mt][1]));
            __stcs(reinterpret_cast<float2*>(orow + 8 * ostride),
                   make_float2(xr[mt][2], xr[mt][3]));
            int pidx = ng * 4 + t;
            xb[r * XSTR + pidx]       = pack_bf16(xr[mt][0], xr[mt][1]);
            xb[(r + 8) * XSTR + pidx] = pack_bf16(xr[mt][2], xr[mt][3]);
        }
        __syncthreads();   // bar C: xb ready for next step
    }
}

extern "C" void kernel_launch(void* const* d_in, const int* in_sizes, int n_in,
                              void* d_out, int out_size)
{
    (void)in_sizes; (void)n_in; (void)out_size;
    const float* x0       = (const float*)d_in[0];
    const float* W1       = (const float*)d_in[1];
    const float* b1       = (const float*)d_in[2];
    const float* W2       = (const float*)d_in[3];
    const float* b2       = (const float*)d_in[4];
    const float* W3       = (const float*)d_in[5];
    const float* b3       = (const float*)d_in[6];
    const float* dt_scale = (const float*)d_in[7];
    const int*   nsteps   = (const int*)d_in[8];
    float*       out      = (float*)d_out;

    cudaFuncSetAttribute(neuralode_persistent_kernel,
                         cudaFuncAttributeMaxDynamicSharedMemorySize, SMEM_BYTES);
    neuralode_persistent_kernel<<<CTAS, NTH, SMEM_BYTES>>>(
        x0, W1, b1, W2, b2, W3, b3, dt_scale, nsteps, out);
}